// round 14
// baseline (speedup 1.0000x reference)
#include <cuda_runtime.h>
#include <cuda_fp16.h>
#include <math.h>

#define NN 100000
#define NE 1600000
#define D 128
#define DOUT 64

// ---------------- scratch (static device globals; no allocs) ----------------
__device__ uint2  d_hx[5][NN * 32];   // pre-scaled states x'_k = norm*x_k, fp16
__device__ int    d_col[NE];          // src index per CSR slot
__device__ __half d_W1h[D * D];
__device__ __half d_W2h[D * DOUT];
__device__ int    d_deg[NN];
__device__ float  d_norm[NN];         // deg^-0.5
__device__ float  d_rnorm[NN];        // deg^+0.5
__device__ int    d_rowptr[NN + 1];
__device__ int    d_cursor[NN];
__device__ int    d_bsums[128];
__device__ int    d_is64;

#define SCAN_B 98
#define FIXUP_B ((NN + 255) / 256)    // 391

// ---------------- zero deg + weight convert + dtype detect ------------------
__global__ void zero_prep_kernel(const int* __restrict__ ei32,
                                 const float* __restrict__ W1,
                                 const float* __restrict__ W2) {
    int i = blockIdx.x * blockDim.x + threadIdx.x;
    if (i < NN) d_deg[i] = 0;
    if (i < D * D) d_W1h[i] = __float2half(W1[i]);
    if (i < D * DOUT) d_W2h[i] = __float2half(W2[i]);
    if (i == 0) {
        int all_zero = 1;
        #pragma unroll
        for (int j = 0; j < 32; j++)
            if (ei32[2 * j + 1] != 0) all_zero = 0;
        d_is64 = all_zero;
    }
}

__device__ __forceinline__ int clampn(int v) {
    return (v < 0) ? 0 : (v >= NN ? NN - 1 : v);
}

// ---------------- CSR build ----------------
// hist: 4 edges per thread
__global__ void hist_kernel(const int* __restrict__ ei32) {
    int q = blockIdx.x * blockDim.x + threadIdx.x;
    int e = q * 4;
    if (e < NE) {
        int d0, d1, d2, d3;
        if (d_is64) {
            int4 a = *(const int4*)&ei32[2 * (NE + e)];
            int4 b = *(const int4*)&ei32[2 * (NE + e) + 4];
            d0 = a.x; d1 = a.z; d2 = b.x; d3 = b.z;
        } else {
            int4 v = *(const int4*)&ei32[NE + e];
            d0 = v.x; d1 = v.y; d2 = v.z; d3 = v.w;
        }
        atomicAdd(&d_deg[clampn(d0)], 1);
        atomicAdd(&d_deg[clampn(d1)], 1);
        atomicAdd(&d_deg[clampn(d2)], 1);
        atomicAdd(&d_deg[clampn(d3)], 1);
    }
}

// per-block prefix (warp-shuffle scan) + norm/rnorm; raw block totals to d_bsums
__global__ void scan1_kernel() {
    __shared__ int wsum[32];
    int tid  = threadIdx.x;
    int lane = tid & 31;
    int wid  = tid >> 5;
    int idx  = blockIdx.x * 1024 + tid;
    int c = (idx < NN) ? d_deg[idx] : 0;
    if (idx < NN) {
        float dg = fmaxf((float)c, 1.0f);
        d_norm[idx]  = rsqrtf(dg);
        d_rnorm[idx] = sqrtf(dg);
    }
    // warp inclusive scan
    int v = c;
    #pragma unroll
    for (int off = 1; off < 32; off <<= 1) {
        int u = __shfl_up_sync(0xFFFFFFFFu, v, off);
        if (lane >= off) v += u;
    }
    if (lane == 31) wsum[wid] = v;
    __syncthreads();
    // scan the 32 warp sums in warp 0
    if (wid == 0) {
        int s = wsum[lane];
        #pragma unroll
        for (int off = 1; off < 32; off <<= 1) {
            int u = __shfl_up_sync(0xFFFFFFFFu, s, off);
            if (lane >= off) s += u;
        }
        wsum[lane] = s;
    }
    __syncthreads();
    int base = (wid > 0) ? wsum[wid - 1] : 0;
    if (idx < NN) d_rowptr[idx] = base + v - c;     // exclusive
    if (tid == 1023) d_bsums[blockIdx.x] = wsum[31];  // block total
}

// merged: scan fix-up (blocks 0..390) + init x'_0 (all 6250 blocks, 32B/thread)
__global__ void post_scan_kernel(const float* __restrict__ feats) {
    __shared__ int red[256];
    int tid = threadIdx.x;
    int b   = blockIdx.x;

    if (b < FIXUP_B) {
        int bucket = b >> 2;                 // (i >> 10), constant per block
        int partial = 0;
        for (int j = tid; j < bucket; j += 256) partial += d_bsums[j];
        red[tid] = partial;
        __syncthreads();
        #pragma unroll
        for (int off = 128; off > 0; off >>= 1) {
            if (tid < off) red[tid] += red[tid + off];
            __syncthreads();
        }
        int base = red[0];
        int i = b * 256 + tid;
        if (i < NN) {
            int r = d_rowptr[i] + base;
            d_rowptr[i] = r;
            d_cursor[i] = r;
        }
        if (i == 0) d_rowptr[NN] = NE;
    }

    // init: x'_0 = fp16(norm * feats), 2 uint2 outputs (32B) per thread
    int j = (b * 256 + tid) * 2;           // uint2 index space NN*32
    if (j < NN * 32) {
        float nw = d_norm[j >> 5];         // j, j+1 same node (32 cols/node)
        float4 va = ((const float4*)feats)[j];
        float4 vb = ((const float4*)feats)[j + 1];
        __half2 p0 = __floats2half2_rn(nw * va.x, nw * va.y);
        __half2 p1 = __floats2half2_rn(nw * va.z, nw * va.w);
        __half2 p2 = __floats2half2_rn(nw * vb.x, nw * vb.y);
        __half2 p3 = __floats2half2_rn(nw * vb.z, nw * vb.w);
        uint4 o;
        o.x = *(unsigned*)&p0; o.y = *(unsigned*)&p1;
        o.z = *(unsigned*)&p2; o.w = *(unsigned*)&p3;
        *(uint4*)&d_hx[0][j] = o;
    }
}

// fill: 4 edges per thread, int4 index loads
__global__ void fill_kernel(const int* __restrict__ ei32) {
    int q = blockIdx.x * blockDim.x + threadIdx.x;
    int e = q * 4;
    if (e < NE) {
        int s0, s1, s2, s3, t0, t1, t2, t3;
        if (d_is64) {
            int4 sa = *(const int4*)&ei32[2 * e];
            int4 sb = *(const int4*)&ei32[2 * e + 4];
            int4 da = *(const int4*)&ei32[2 * (NE + e)];
            int4 db = *(const int4*)&ei32[2 * (NE + e) + 4];
            s0 = sa.x; s1 = sa.z; s2 = sb.x; s3 = sb.z;
            t0 = da.x; t1 = da.z; t2 = db.x; t3 = db.z;
        } else {
            int4 sv = *(const int4*)&ei32[e];
            int4 dv = *(const int4*)&ei32[NE + e];
            s0 = sv.x; s1 = sv.y; s2 = sv.z; s3 = sv.w;
            t0 = dv.x; t1 = dv.y; t2 = dv.z; t3 = dv.w;
        }
        s0 = clampn(s0); s1 = clampn(s1); s2 = clampn(s2); s3 = clampn(s3);
        t0 = clampn(t0); t1 = clampn(t1); t2 = clampn(t2); t3 = clampn(t3);
        int p0 = atomicAdd(&d_cursor[t0], 1); if (p0 < NE) d_col[p0] = s0;
        int p1 = atomicAdd(&d_cursor[t1], 1); if (p1 < NE) d_col[p1] = s1;
        int p2 = atomicAdd(&d_cursor[t2], 1); if (p2 < NE) d_col[p2] = s2;
        int p3 = atomicAdd(&d_cursor[t3], 1); if (p3 < NE) d_col[p3] = s3;
    }
}

// ---------------- propagation: warp per node, 2 edges per LDG.128 -----------
// (R7/R9/R10 structure — empirical optimum; DO NOT MODIFY)
__device__ __forceinline__ void acc8(float* a, uint4 v) {
    float2 f;
    f = __half22float2(*(__half2*)&v.x); a[0] += f.x; a[1] += f.y;
    f = __half22float2(*(__half2*)&v.y); a[2] += f.x; a[3] += f.y;
    f = __half22float2(*(__half2*)&v.z); a[4] += f.x; a[5] += f.y;
    f = __half22float2(*(__half2*)&v.w); a[6] += f.x; a[7] += f.y;
}

__global__ void __launch_bounds__(256) propagate_kernel(int k) {
    const uint4* __restrict__ xin  = (const uint4*)d_hx[k - 1];
    uint4* __restrict__       xout = (uint4*)d_hx[k];

    int warp = (blockIdx.x * blockDim.x + threadIdx.x) >> 5;
    int lane = threadIdx.x & 31;
    if (warp >= NN) return;
    int sub = lane >> 4;       // 0 or 1
    int sl  = lane & 15;       // uint4 column within node row

    int beg = d_rowptr[warp];
    int end = d_rowptr[warp + 1];
    float a[8] = {0.f, 0.f, 0.f, 0.f, 0.f, 0.f, 0.f, 0.f};

    int e = beg;
    for (; e + 8 <= end; e += 8) {
        int s0 = d_col[e + 0], s1 = d_col[e + 1];
        int s2 = d_col[e + 2], s3 = d_col[e + 3];
        int s4 = d_col[e + 4], s5 = d_col[e + 5];
        int s6 = d_col[e + 6], s7 = d_col[e + 7];
        uint4 v0 = xin[(sub ? s1 : s0) * 16 + sl];
        uint4 v1 = xin[(sub ? s3 : s2) * 16 + sl];
        uint4 v2 = xin[(sub ? s5 : s4) * 16 + sl];
        uint4 v3 = xin[(sub ? s7 : s6) * 16 + sl];
        acc8(a, v0); acc8(a, v1); acc8(a, v2); acc8(a, v3);
    }
    for (; e + 2 <= end; e += 2) {
        int sa = d_col[e], sb = d_col[e + 1];
        uint4 v = xin[(sub ? sb : sa) * 16 + sl];
        acc8(a, v);
    }
    if (e < end && sub == 0) {
        uint4 v = xin[d_col[e] * 16 + sl];
        acc8(a, v);
    }

    #pragma unroll
    for (int j = 0; j < 8; j++)
        a[j] += __shfl_xor_sync(0xFFFFFFFFu, a[j], 16);

    if (sub == 0) {
        float nw = d_norm[warp];
        float w2 = nw * nw;
        __half2 h0 = __floats2half2_rn(w2 * a[0], w2 * a[1]);
        __half2 h1 = __floats2half2_rn(w2 * a[2], w2 * a[3]);
        __half2 h2 = __floats2half2_rn(w2 * a[4], w2 * a[5]);
        __half2 h3 = __floats2half2_rn(w2 * a[6], w2 * a[7]);
        uint4 o;
        o.x = *(unsigned*)&h0; o.y = *(unsigned*)&h1;
        o.z = *(unsigned*)&h2; o.w = *(unsigned*)&h3;
        xout[warp * 16 + sl] = o;
    }
}

// ---------------- tensor-core fused MLP ------------------------------------
// out = relu((0.1 * rnorm_i * sum_b x'_b) @ W1) @ W2
#define YST  136
#define W1ST 136
#define W2ST 72
#define HST  136
#define OFF_W1 0
#define OFF_W2 17408
#define OFF_Y  26624
#define OFF_H  35328
#define GEMM_SMEM (44032 * 2)

__device__ __forceinline__ void ldsm_x4(unsigned addr, unsigned& r0, unsigned& r1,
                                        unsigned& r2, unsigned& r3) {
    asm volatile("ldmatrix.sync.aligned.m8n8.x4.shared.b16 {%0,%1,%2,%3}, [%4];"
                 : "=r"(r0), "=r"(r1), "=r"(r2), "=r"(r3) : "r"(addr));
}
__device__ __forceinline__ void ldsm_x2t(unsigned addr, unsigned& r0, unsigned& r1) {
    asm volatile("ldmatrix.sync.aligned.m8n8.x2.trans.shared.b16 {%0,%1}, [%2];"
                 : "=r"(r0), "=r"(r1) : "r"(addr));
}
__device__ __forceinline__ void mma_16816(float& d0, float& d1, float& d2, float& d3,
                                          unsigned a0, unsigned a1, unsigned a2, unsigned a3,
                                          unsigned b0, unsigned b1) {
    asm volatile("mma.sync.aligned.m16n8k16.row.col.f32.f16.f16.f32 "
                 "{%0,%1,%2,%3}, {%4,%5,%6,%7}, {%8,%9}, {%0,%1,%2,%3};"
                 : "+f"(d0), "+f"(d1), "+f"(d2), "+f"(d3)
                 : "r"(a0), "r"(a1), "r"(a2), "r"(a3), "r"(b0), "r"(b1));
}

__global__ void gemm_fused_kernel(float* __restrict__ out) {
    extern __shared__ __half sh[];
    unsigned sbase = (unsigned)__cvta_generic_to_shared(sh);

    int t = threadIdx.x;        // 128 threads, 4 warps
    int lane = t & 31;
    int w = t >> 5;
    int rowBase = blockIdx.x * 64;

    {
        const uint4* g = (const uint4*)d_W1h;
        #pragma unroll
        for (int i = 0; i < 16; i++) {
            int idx = i * 128 + t;
            int r = idx >> 4, c4 = idx & 15;
            *(uint4*)&sh[OFF_W1 + r * W1ST + c4 * 8] = g[idx];
        }
    }
    {
        const uint4* g = (const uint4*)d_W2h;
        #pragma unroll
        for (int i = 0; i < 8; i++) {
            int idx = i * 128 + t;
            int r = idx >> 3, c4 = idx & 7;
            *(uint4*)&sh[OFF_W2 + r * W2ST + c4 * 8] = g[idx];
        }
    }
    // ---- build Y tile = fp16(0.1 * rnorm * sum_b x'_b) ----
    {
        #pragma unroll
        for (int i = 0; i < 16; i++) {
            int idx = i * 128 + t;          // 64 rows x 32 uint2 cols
            int r = idx >> 5, c = idx & 31;
            int gr = rowBase + r;
            float s0 = 0.f, s1 = 0.f, s2 = 0.f, s3 = 0.f;
            float scl = 0.f;
            if (gr < NN) {
                scl = 0.1f * d_rnorm[gr];
                #pragma unroll
                for (int b = 0; b < 5; b++) {
                    uint2 v = d_hx[b][gr * 32 + c];
                    float2 f0 = __half22float2(*(__half2*)&v.x);
                    float2 f1 = __half22float2(*(__half2*)&v.y);
                    s0 += f0.x; s1 += f0.y; s2 += f1.x; s3 += f1.y;
                }
            }
            __half2 p0 = __floats2half2_rn(scl * s0, scl * s1);
            __half2 p1 = __floats2half2_rn(scl * s2, scl * s3);
            uint2 o;
            o.x = *(unsigned*)&p0;
            o.y = *(unsigned*)&p1;
            *(uint2*)&sh[OFF_Y + r * YST + c * 4] = o;
        }
    }
    __syncthreads();

    int g_  = lane >> 3;
    int ar  = (g_ & 1) * 8 + (lane & 7);
    int ac  = (g_ >> 1) * 8;
    int bk  = lane & 15;

    // ---- phase A: H = relu(Y @ W1) ----
    {
        unsigned aF[8][4];
        #pragma unroll
        for (int ks = 0; ks < 8; ks++) {
            unsigned addr = sbase + (OFF_Y + (w * 16 + ar) * YST + ks * 16 + ac) * 2;
            ldsm_x4(addr, aF[ks][0], aF[ks][1], aF[ks][2], aF[ks][3]);
        }
        #pragma unroll
        for (int nt = 0; nt < 16; nt++) {
            float d0 = 0.f, d1 = 0.f, d2 = 0.f, d3 = 0.f;
            #pragma unroll
            for (int ks = 0; ks < 8; ks++) {
                unsigned b0, b1;
                unsigned baddr = sbase + (OFF_W1 + (ks * 16 + bk) * W1ST + nt * 8) * 2;
                ldsm_x2t(baddr, b0, b1);
                mma_16816(d0, d1, d2, d3, aF[ks][0], aF[ks][1], aF[ks][2], aF[ks][3], b0, b1);
            }
            int hr = w * 16 + (lane >> 2);
            int hc = nt * 8 + (lane & 3) * 2;
            __half2 h01 = __floats2half2_rn(fmaxf(d0, 0.f), fmaxf(d1, 0.f));
            __half2 h23 = __floats2half2_rn(fmaxf(d2, 0.f), fmaxf(d3, 0.f));
            *(unsigned*)&sh[OFF_H + hr * HST + hc]       = *(unsigned*)&h01;
            *(unsigned*)&sh[OFF_H + (hr + 8) * HST + hc] = *(unsigned*)&h23;
        }
    }
    __syncthreads();

    // ---- phase B: out = H @ W2 ----
    {
        unsigned hF[8][4];
        #pragma unroll
        for (int ks = 0; ks < 8; ks++) {
            unsigned addr = sbase + (OFF_H + (w * 16 + ar) * HST + ks * 16 + ac) * 2;
            ldsm_x4(addr, hF[ks][0], hF[ks][1], hF[ks][2], hF[ks][3]);
        }
        #pragma unroll
        for (int nt = 0; nt < 8; nt++) {
            float d0 = 0.f, d1 = 0.f, d2 = 0.f, d3 = 0.f;
            #pragma unroll
            for (int ks = 0; ks < 8; ks++) {
                unsigned b0, b1;
                unsigned baddr = sbase + (OFF_W2 + (ks * 16 + bk) * W2ST + nt * 8) * 2;
                ldsm_x2t(baddr, b0, b1);
                mma_16816(d0, d1, d2, d3, hF[ks][0], hF[ks][1], hF[ks][2], hF[ks][3], b0, b1);
            }
            int row = w * 16 + (lane >> 2);
            int c   = nt * 8 + (lane & 3) * 2;
            int gr0 = rowBase + row;
            int gr1 = gr0 + 8;
            if (gr0 < NN) *(float2*)&out[gr0 * DOUT + c] = make_float2(d0, d1);
            if (gr1 < NN) *(float2*)&out[gr1 * DOUT + c] = make_float2(d2, d3);
        }
    }
}

// ---------------- launch ----------------
extern "C" void kernel_launch(void* const* d_in, const int* in_sizes, int n_in,
                              void* d_out, int out_size) {
    const float* feats = (const float*)d_in[0];
    const float* W1    = (const float*)d_in[1];
    const float* W2    = (const float*)d_in[2];
    const int*   ei32  = (const int*)d_in[3];
    float*       out   = (float*)d_out;

    cudaFuncSetAttribute(gemm_fused_kernel,
                         cudaFuncAttributeMaxDynamicSharedMemorySize, GEMM_SMEM);

    zero_prep_kernel<<<(NN + 255) / 256, 256>>>(ei32, W1, W2);
    hist_kernel<<<(NE / 4 + 255) / 256, 256>>>(ei32);
    scan1_kernel<<<SCAN_B, 1024>>>();
    post_scan_kernel<<<(NN * 16 + 255) / 256, 256>>>(feats);   // fixup + init
    fill_kernel<<<(NE / 4 + 255) / 256, 256>>>(ei32);

    int prop_grid = (NN * 32 + 255) / 256;
    propagate_kernel<<<prop_grid, 256>>>(1);
    propagate_kernel<<<prop_grid, 256>>>(2);
    propagate_kernel<<<prop_grid, 256>>>(3);
    propagate_kernel<<<prop_grid, 256>>>(4);

    gemm_fused_kernel<<<(NN + 63) / 64, 128, GEMM_SMEM>>>(out);
}

// round 15
// speedup vs baseline: 1.0056x; 1.0056x over previous
#include <cuda_runtime.h>
#include <cuda_fp16.h>
#include <math.h>

#define NN 100000
#define NE 1600000
#define D 128
#define DOUT 64

// ---------------- scratch (static device globals; no allocs) ----------------
__device__ uint2  d_hx[5][NN * 32];   // pre-scaled states x'_k = norm*x_k, fp16
__device__ int    d_col[NE];          // src index per CSR slot
__device__ __half d_W1h[D * D];
__device__ __half d_W2h[D * DOUT];
__device__ int    d_deg[NN];
__device__ float  d_norm[NN];         // deg^-0.5
__device__ float  d_rnorm[NN];        // deg^+0.5
__device__ int    d_rowptr[NN + 1];
__device__ int    d_cursor[NN];
__device__ int    d_bsums[128];
__device__ int    d_is64;

#define SCAN_B 98
#define FIXUP_B ((NN + 255) / 256)    // 391

// ---------------- zero deg + weight convert + dtype detect ------------------
__global__ void zero_prep_kernel(const int* __restrict__ ei32,
                                 const float* __restrict__ W1,
                                 const float* __restrict__ W2) {
    int i = blockIdx.x * blockDim.x + threadIdx.x;
    if (i < NN) d_deg[i] = 0;
    if (i < D * D) d_W1h[i] = __float2half(W1[i]);
    if (i < D * DOUT) d_W2h[i] = __float2half(W2[i]);
    if (i == 0) {
        int all_zero = 1;
        #pragma unroll
        for (int j = 0; j < 32; j++)
            if (ei32[2 * j + 1] != 0) all_zero = 0;
        d_is64 = all_zero;
    }
}

__device__ __forceinline__ int clampn(int v) {
    return (v < 0) ? 0 : (v >= NN ? NN - 1 : v);
}

// ---------------- CSR build ----------------
// hist: 4 edges per thread
__global__ void hist_kernel(const int* __restrict__ ei32) {
    int q = blockIdx.x * blockDim.x + threadIdx.x;
    int e = q * 4;
    if (e < NE) {
        int d0, d1, d2, d3;
        if (d_is64) {
            int4 a = *(const int4*)&ei32[2 * (NE + e)];
            int4 b = *(const int4*)&ei32[2 * (NE + e) + 4];
            d0 = a.x; d1 = a.z; d2 = b.x; d3 = b.z;
        } else {
            int4 v = *(const int4*)&ei32[NE + e];
            d0 = v.x; d1 = v.y; d2 = v.z; d3 = v.w;
        }
        atomicAdd(&d_deg[clampn(d0)], 1);
        atomicAdd(&d_deg[clampn(d1)], 1);
        atomicAdd(&d_deg[clampn(d2)], 1);
        atomicAdd(&d_deg[clampn(d3)], 1);
    }
}

// per-block prefix + norm/rnorm; raw block totals to d_bsums
__global__ void scan1_kernel() {
    __shared__ int s[1024];
    int tid = threadIdx.x;
    int idx = blockIdx.x * 1024 + tid;
    int c = (idx < NN) ? d_deg[idx] : 0;
    if (idx < NN) {
        float dg = fmaxf((float)c, 1.0f);
        d_norm[idx]  = rsqrtf(dg);
        d_rnorm[idx] = sqrtf(dg);
    }
    s[tid] = c;
    __syncthreads();
    #pragma unroll
    for (int off = 1; off < 1024; off <<= 1) {
        int v = (tid >= off) ? s[tid - off] : 0;
        __syncthreads();
        s[tid] += v;
        __syncthreads();
    }
    if (idx < NN) d_rowptr[idx] = s[tid] - c;
    if (tid == 1023) d_bsums[blockIdx.x] = s[1023];   // raw totals
}

// merged: scan fix-up (blocks 0..390) + init x'_0 (all 6250 blocks, 32B/thread)
__global__ void post_scan_kernel(const float* __restrict__ feats) {
    __shared__ int red[256];
    int tid = threadIdx.x;
    int b   = blockIdx.x;

    if (b < FIXUP_B) {
        int bucket = b >> 2;                 // (i >> 10), constant per block
        int partial = 0;
        for (int j = tid; j < bucket; j += 256) partial += d_bsums[j];
        red[tid] = partial;
        __syncthreads();
        #pragma unroll
        for (int off = 128; off > 0; off >>= 1) {
            if (tid < off) red[tid] += red[tid + off];
            __syncthreads();
        }
        int base = red[0];
        int i = b * 256 + tid;
        if (i < NN) {
            int r = d_rowptr[i] + base;
            d_rowptr[i] = r;
            d_cursor[i] = r;
        }
        if (i == 0) d_rowptr[NN] = NE;
    }

    // init: x'_0 = fp16(norm * feats), 2 uint2 outputs (32B) per thread
    int j = (b * 256 + tid) * 2;           // uint2 index space NN*32
    if (j < NN * 32) {
        float nw = d_norm[j >> 5];         // j, j+1 same node (32 cols/node)
        float4 va = ((const float4*)feats)[j];
        float4 vb = ((const float4*)feats)[j + 1];
        __half2 p0 = __floats2half2_rn(nw * va.x, nw * va.y);
        __half2 p1 = __floats2half2_rn(nw * va.z, nw * va.w);
        __half2 p2 = __floats2half2_rn(nw * vb.x, nw * vb.y);
        __half2 p3 = __floats2half2_rn(nw * vb.z, nw * vb.w);
        uint4 o;
        o.x = *(unsigned*)&p0; o.y = *(unsigned*)&p1;
        o.z = *(unsigned*)&p2; o.w = *(unsigned*)&p3;
        *(uint4*)&d_hx[0][j] = o;
    }
}

// fill: 2 edges per thread, vectorized index loads
__global__ void fill_kernel(const int* __restrict__ ei32) {
    int p = blockIdx.x * blockDim.x + threadIdx.x;
    int e = p * 2;
    if (e < NE) {
        int sA, sB, dA, dB;
        if (d_is64) {
            int4 sv = *(const int4*)&ei32[2 * e];
            int4 dv = *(const int4*)&ei32[2 * (NE + e)];
            sA = sv.x; sB = sv.z; dA = dv.x; dB = dv.z;
        } else {
            int2 sv = *(const int2*)&ei32[e];
            int2 dv = *(const int2*)&ei32[NE + e];
            sA = sv.x; sB = sv.y; dA = dv.x; dB = dv.y;
        }
        sA = clampn(sA); sB = clampn(sB);
        dA = clampn(dA); dB = clampn(dB);
        int pA = atomicAdd(&d_cursor[dA], 1);
        if (pA < NE) d_col[pA] = sA;
        int pB = atomicAdd(&d_cursor[dB], 1);
        if (pB < NE) d_col[pB] = sB;
    }
}

// ---------------- propagation: warp per node, 2 edges per LDG.128 -----------
// (R7/R9/R10 structure — empirical optimum; DO NOT MODIFY)
__device__ __forceinline__ void acc8(float* a, uint4 v) {
    float2 f;
    f = __half22float2(*(__half2*)&v.x); a[0] += f.x; a[1] += f.y;
    f = __half22float2(*(__half2*)&v.y); a[2] += f.x; a[3] += f.y;
    f = __half22float2(*(__half2*)&v.z); a[4] += f.x; a[5] += f.y;
    f = __half22float2(*(__half2*)&v.w); a[6] += f.x; a[7] += f.y;
}

__global__ void __launch_bounds__(256) propagate_kernel(int k) {
    const uint4* __restrict__ xin  = (const uint4*)d_hx[k - 1];
    uint4* __restrict__       xout = (uint4*)d_hx[k];

    int warp = (blockIdx.x * blockDim.x + threadIdx.x) >> 5;
    int lane = threadIdx.x & 31;
    if (warp >= NN) return;
    int sub = lane >> 4;       // 0 or 1
    int sl  = lane & 15;       // uint4 column within node row

    int beg = d_rowptr[warp];
    int end = d_rowptr[warp + 1];
    float a[8] = {0.f, 0.f, 0.f, 0.f, 0.f, 0.f, 0.f, 0.f};

    int e = beg;
    for (; e + 8 <= end; e += 8) {
        int s0 = d_col[e + 0], s1 = d_col[e + 1];
        int s2 = d_col[e + 2], s3 = d_col[e + 3];
        int s4 = d_col[e + 4], s5 = d_col[e + 5];
        int s6 = d_col[e + 6], s7 = d_col[e + 7];
        uint4 v0 = xin[(sub ? s1 : s0) * 16 + sl];
        uint4 v1 = xin[(sub ? s3 : s2) * 16 + sl];
        uint4 v2 = xin[(sub ? s5 : s4) * 16 + sl];
        uint4 v3 = xin[(sub ? s7 : s6) * 16 + sl];
        acc8(a, v0); acc8(a, v1); acc8(a, v2); acc8(a, v3);
    }
    for (; e + 2 <= end; e += 2) {
        int sa = d_col[e], sb = d_col[e + 1];
        uint4 v = xin[(sub ? sb : sa) * 16 + sl];
        acc8(a, v);
    }
    if (e < end && sub == 0) {
        uint4 v = xin[d_col[e] * 16 + sl];
        acc8(a, v);
    }

    #pragma unroll
    for (int j = 0; j < 8; j++)
        a[j] += __shfl_xor_sync(0xFFFFFFFFu, a[j], 16);

    if (sub == 0) {
        float nw = d_norm[warp];
        float w2 = nw * nw;
        __half2 h0 = __floats2half2_rn(w2 * a[0], w2 * a[1]);
        __half2 h1 = __floats2half2_rn(w2 * a[2], w2 * a[3]);
        __half2 h2 = __floats2half2_rn(w2 * a[4], w2 * a[5]);
        __half2 h3 = __floats2half2_rn(w2 * a[6], w2 * a[7]);
        uint4 o;
        o.x = *(unsigned*)&h0; o.y = *(unsigned*)&h1;
        o.z = *(unsigned*)&h2; o.w = *(unsigned*)&h3;
        xout[warp * 16 + sl] = o;
    }
}

// ---------------- tensor-core fused MLP ------------------------------------
// out = relu((0.1 * rnorm_i * sum_b x'_b) @ W1) @ W2
#define YST  136
#define W1ST 136
#define W2ST 72
#define HST  136
#define OFF_W1 0
#define OFF_W2 17408
#define OFF_Y  26624
#define OFF_H  35328
#define GEMM_SMEM (44032 * 2)

__device__ __forceinline__ void ldsm_x4(unsigned addr, unsigned& r0, unsigned& r1,
                                        unsigned& r2, unsigned& r3) {
    asm volatile("ldmatrix.sync.aligned.m8n8.x4.shared.b16 {%0,%1,%2,%3}, [%4];"
                 : "=r"(r0), "=r"(r1), "=r"(r2), "=r"(r3) : "r"(addr));
}
__device__ __forceinline__ void ldsm_x2t(unsigned addr, unsigned& r0, unsigned& r1) {
    asm volatile("ldmatrix.sync.aligned.m8n8.x2.trans.shared.b16 {%0,%1}, [%2];"
                 : "=r"(r0), "=r"(r1) : "r"(addr));
}
__device__ __forceinline__ void mma_16816(float& d0, float& d1, float& d2, float& d3,
                                          unsigned a0, unsigned a1, unsigned a2, unsigned a3,
                                          unsigned b0, unsigned b1) {
    asm volatile("mma.sync.aligned.m16n8k16.row.col.f32.f16.f16.f32 "
                 "{%0,%1,%2,%3}, {%4,%5,%6,%7}, {%8,%9}, {%0,%1,%2,%3};"
                 : "+f"(d0), "+f"(d1), "+f"(d2), "+f"(d3)
                 : "r"(a0), "r"(a1), "r"(a2), "r"(a3), "r"(b0), "r"(b1));
}

__global__ void gemm_fused_kernel(float* __restrict__ out) {
    extern __shared__ __half sh[];
    unsigned sbase = (unsigned)__cvta_generic_to_shared(sh);

    int t = threadIdx.x;        // 128 threads, 4 warps
    int lane = t & 31;
    int w = t >> 5;
    int rowBase = blockIdx.x * 64;

    {
        const uint4* g = (const uint4*)d_W1h;
        #pragma unroll
        for (int i = 0; i < 16; i++) {
            int idx = i * 128 + t;
            int r = idx >> 4, c4 = idx & 15;
            *(uint4*)&sh[OFF_W1 + r * W1ST + c4 * 8] = g[idx];
        }
    }
    {
        const uint4* g = (const uint4*)d_W2h;
        #pragma unroll
        for (int i = 0; i < 8; i++) {
            int idx = i * 128 + t;
            int r = idx >> 3, c4 = idx & 7;
            *(uint4*)&sh[OFF_W2 + r * W2ST + c4 * 8] = g[idx];
        }
    }
    // ---- build Y tile = fp16(0.1 * rnorm * sum_b x'_b) ----
    {
        #pragma unroll
        for (int i = 0; i < 16; i++) {
            int idx = i * 128 + t;          // 64 rows x 32 uint2 cols
            int r = idx >> 5, c = idx & 31;
            int gr = rowBase + r;
            float s0 = 0.f, s1 = 0.f, s2 = 0.f, s3 = 0.f;
            float scl = 0.f;
            if (gr < NN) {
                scl = 0.1f * d_rnorm[gr];
                #pragma unroll
                for (int b = 0; b < 5; b++) {
                    uint2 v = d_hx[b][gr * 32 + c];
                    float2 f0 = __half22float2(*(__half2*)&v.x);
                    float2 f1 = __half22float2(*(__half2*)&v.y);
                    s0 += f0.x; s1 += f0.y; s2 += f1.x; s3 += f1.y;
                }
            }
            __half2 p0 = __floats2half2_rn(scl * s0, scl * s1);
            __half2 p1 = __floats2half2_rn(scl * s2, scl * s3);
            uint2 o;
            o.x = *(unsigned*)&p0;
            o.y = *(unsigned*)&p1;
            *(uint2*)&sh[OFF_Y + r * YST + c * 4] = o;
        }
    }
    __syncthreads();

    int g_  = lane >> 3;
    int ar  = (g_ & 1) * 8 + (lane & 7);
    int ac  = (g_ >> 1) * 8;
    int bk  = lane & 15;

    // ---- phase A: H = relu(Y @ W1) ----
    {
        unsigned aF[8][4];
        #pragma unroll
        for (int ks = 0; ks < 8; ks++) {
            unsigned addr = sbase + (OFF_Y + (w * 16 + ar) * YST + ks * 16 + ac) * 2;
            ldsm_x4(addr, aF[ks][0], aF[ks][1], aF[ks][2], aF[ks][3]);
        }
        #pragma unroll
        for (int nt = 0; nt < 16; nt++) {
            float d0 = 0.f, d1 = 0.f, d2 = 0.f, d3 = 0.f;
            #pragma unroll
            for (int ks = 0; ks < 8; ks++) {
                unsigned b0, b1;
                unsigned baddr = sbase + (OFF_W1 + (ks * 16 + bk) * W1ST + nt * 8) * 2;
                ldsm_x2t(baddr, b0, b1);
                mma_16816(d0, d1, d2, d3, aF[ks][0], aF[ks][1], aF[ks][2], aF[ks][3], b0, b1);
            }
            int hr = w * 16 + (lane >> 2);
            int hc = nt * 8 + (lane & 3) * 2;
            __half2 h01 = __floats2half2_rn(fmaxf(d0, 0.f), fmaxf(d1, 0.f));
            __half2 h23 = __floats2half2_rn(fmaxf(d2, 0.f), fmaxf(d3, 0.f));
            *(unsigned*)&sh[OFF_H + hr * HST + hc]       = *(unsigned*)&h01;
            *(unsigned*)&sh[OFF_H + (hr + 8) * HST + hc] = *(unsigned*)&h23;
        }
    }
    __syncthreads();

    // ---- phase B: out = H @ W2 ----
    {
        unsigned hF[8][4];
        #pragma unroll
        for (int ks = 0; ks < 8; ks++) {
            unsigned addr = sbase + (OFF_H + (w * 16 + ar) * HST + ks * 16 + ac) * 2;
            ldsm_x4(addr, hF[ks][0], hF[ks][1], hF[ks][2], hF[ks][3]);
        }
        #pragma unroll
        for (int nt = 0; nt < 8; nt++) {
            float d0 = 0.f, d1 = 0.f, d2 = 0.f, d3 = 0.f;
            #pragma unroll
            for (int ks = 0; ks < 8; ks++) {
                unsigned b0, b1;
                unsigned baddr = sbase + (OFF_W2 + (ks * 16 + bk) * W2ST + nt * 8) * 2;
                ldsm_x2t(baddr, b0, b1);
                mma_16816(d0, d1, d2, d3, hF[ks][0], hF[ks][1], hF[ks][2], hF[ks][3], b0, b1);
            }
            int row = w * 16 + (lane >> 2);
            int c   = nt * 8 + (lane & 3) * 2;
            int gr0 = rowBase + row;
            int gr1 = gr0 + 8;
            if (gr0 < NN) *(float2*)&out[gr0 * DOUT + c] = make_float2(d0, d1);
            if (gr1 < NN) *(float2*)&out[gr1 * DOUT + c] = make_float2(d2, d3);
        }
    }
}

// ---------------- launch ----------------
extern "C" void kernel_launch(void* const* d_in, const int* in_sizes, int n_in,
                              void* d_out, int out_size) {
    const float* feats = (const float*)d_in[0];
    const float* W1    = (const float*)d_in[1];
    const float* W2    = (const float*)d_in[2];
    const int*   ei32  = (const int*)d_in[3];
    float*       out   = (float*)d_out;

    cudaFuncSetAttribute(gemm_fused_kernel,
                         cudaFuncAttributeMaxDynamicSharedMemorySize, GEMM_SMEM);

    zero_prep_kernel<<<(NN + 255) / 256, 256>>>(ei32, W1, W2);
    hist_kernel<<<(NE / 4 + 255) / 256, 256>>>(ei32);
    scan1_kernel<<<SCAN_B, 1024>>>();
    post_scan_kernel<<<(NN * 16 + 255) / 256, 256>>>(feats);   // fixup + init
    fill_kernel<<<(NE / 2 + 255) / 256, 256>>>(ei32);

    int prop_grid = (NN * 32 + 255) / 256;
    propagate_kernel<<<prop_grid, 256>>>(1);
    propagate_kernel<<<prop_grid, 256>>>(2);
    propagate_kernel<<<prop_grid, 256>>>(3);
    propagate_kernel<<<prop_grid, 256>>>(4);

    gemm_fused_kernel<<<(NN + 63) / 64, 128, GEMM_SMEM>>>(out);
}

// round 16
// speedup vs baseline: 1.0397x; 1.0338x over previous
#include <cuda_runtime.h>
#include <cuda_fp16.h>
#include <math.h>

#define NN 100000
#define NE 1600000
#define D 128
#define DOUT 64

// ---------------- scratch (static device globals; no allocs) ----------------
__device__ uint2  d_hx[5][NN * 32];   // pre-scaled states x'_k = norm*x_k, fp16
__device__ int    d_col[NE];          // src index per CSR slot
__device__ __half d_W1h[D * D];
__device__ __half d_W2h[D * DOUT];
__device__ int    d_deg[NN];
__device__ float  d_norm[NN];         // deg^-0.5
__device__ float  d_rnorm[NN];        // deg^+0.5
__device__ int    d_rowptr[NN + 1];
__device__ int    d_cursor[NN];
__device__ int    d_bsums[128];
__device__ int    d_is64;

#define SCAN_B 98
#define FIXUP_B ((NN + 255) / 256)    // 391

// ---------------- zero deg + weight convert + dtype detect ------------------
__global__ void zero_prep_kernel(const int* __restrict__ ei32,
                                 const float* __restrict__ W1,
                                 const float* __restrict__ W2) {
    int i = blockIdx.x * blockDim.x + threadIdx.x;
    if (i < NN) d_deg[i] = 0;
    if (i < D * D) d_W1h[i] = __float2half(W1[i]);
    if (i < D * DOUT) d_W2h[i] = __float2half(W2[i]);
    if (i == 0) {
        int all_zero = 1;
        #pragma unroll
        for (int j = 0; j < 32; j++)
            if (ei32[2 * j + 1] != 0) all_zero = 0;
        d_is64 = all_zero;
    }
}

__device__ __forceinline__ int clampn(int v) {
    return (v < 0) ? 0 : (v >= NN ? NN - 1 : v);
}

// ---------------- CSR build ----------------
// hist: 4 edges per thread
__global__ void hist_kernel(const int* __restrict__ ei32) {
    int q = blockIdx.x * blockDim.x + threadIdx.x;
    int e = q * 4;
    if (e < NE) {
        int d0, d1, d2, d3;
        if (d_is64) {
            int4 a = *(const int4*)&ei32[2 * (NE + e)];
            int4 b = *(const int4*)&ei32[2 * (NE + e) + 4];
            d0 = a.x; d1 = a.z; d2 = b.x; d3 = b.z;
        } else {
            int4 v = *(const int4*)&ei32[NE + e];
            d0 = v.x; d1 = v.y; d2 = v.z; d3 = v.w;
        }
        atomicAdd(&d_deg[clampn(d0)], 1);
        atomicAdd(&d_deg[clampn(d1)], 1);
        atomicAdd(&d_deg[clampn(d2)], 1);
        atomicAdd(&d_deg[clampn(d3)], 1);
    }
}

// per-block prefix + norm/rnorm; raw block totals to d_bsums
__global__ void scan1_kernel() {
    __shared__ int s[1024];
    int tid = threadIdx.x;
    int idx = blockIdx.x * 1024 + tid;
    int c = (idx < NN) ? d_deg[idx] : 0;
    if (idx < NN) {
        float dg = fmaxf((float)c, 1.0f);
        d_norm[idx]  = rsqrtf(dg);
        d_rnorm[idx] = sqrtf(dg);
    }
    s[tid] = c;
    __syncthreads();
    #pragma unroll
    for (int off = 1; off < 1024; off <<= 1) {
        int v = (tid >= off) ? s[tid - off] : 0;
        __syncthreads();
        s[tid] += v;
        __syncthreads();
    }
    if (idx < NN) d_rowptr[idx] = s[tid] - c;
    if (tid == 1023) d_bsums[blockIdx.x] = s[1023];   // raw totals
}

// merged: scan fix-up (blocks 0..390) + init x'_0 (all 6250 blocks, 32B/thread)
__global__ void post_scan_kernel(const float* __restrict__ feats) {
    __shared__ int red[256];
    int tid = threadIdx.x;
    int b   = blockIdx.x;

    if (b < FIXUP_B) {
        int bucket = b >> 2;                 // (i >> 10), constant per block
        int partial = 0;
        for (int j = tid; j < bucket; j += 256) partial += d_bsums[j];
        red[tid] = partial;
        __syncthreads();
        #pragma unroll
        for (int off = 128; off > 0; off >>= 1) {
            if (tid < off) red[tid] += red[tid + off];
            __syncthreads();
        }
        int base = red[0];
        int i = b * 256 + tid;
        if (i < NN) {
            int r = d_rowptr[i] + base;
            d_rowptr[i] = r;
            d_cursor[i] = r;
        }
        if (i == 0) d_rowptr[NN] = NE;
    }

    // init: x'_0 = fp16(norm * feats), 2 uint2 outputs (32B) per thread
    int j = (b * 256 + tid) * 2;           // uint2 index space NN*32
    if (j < NN * 32) {
        float nw = d_norm[j >> 5];         // j, j+1 same node (32 cols/node)
        float4 va = ((const float4*)feats)[j];
        float4 vb = ((const float4*)feats)[j + 1];
        __half2 p0 = __floats2half2_rn(nw * va.x, nw * va.y);
        __half2 p1 = __floats2half2_rn(nw * va.z, nw * va.w);
        __half2 p2 = __floats2half2_rn(nw * vb.x, nw * vb.y);
        __half2 p3 = __floats2half2_rn(nw * vb.z, nw * vb.w);
        uint4 o;
        o.x = *(unsigned*)&p0; o.y = *(unsigned*)&p1;
        o.z = *(unsigned*)&p2; o.w = *(unsigned*)&p3;
        *(uint4*)&d_hx[0][j] = o;
    }
}

// fill: 2 edges per thread, vectorized index loads
__global__ void fill_kernel(const int* __restrict__ ei32) {
    int p = blockIdx.x * blockDim.x + threadIdx.x;
    int e = p * 2;
    if (e < NE) {
        int sA, sB, dA, dB;
        if (d_is64) {
            int4 sv = *(const int4*)&ei32[2 * e];
            int4 dv = *(const int4*)&ei32[2 * (NE + e)];
            sA = sv.x; sB = sv.z; dA = dv.x; dB = dv.z;
        } else {
            int2 sv = *(const int2*)&ei32[e];
            int2 dv = *(const int2*)&ei32[NE + e];
            sA = sv.x; sB = sv.y; dA = dv.x; dB = dv.y;
        }
        sA = clampn(sA); sB = clampn(sB);
        dA = clampn(dA); dB = clampn(dB);
        int pA = atomicAdd(&d_cursor[dA], 1);
        if (pA < NE) d_col[pA] = sA;
        int pB = atomicAdd(&d_cursor[dB], 1);
        if (pB < NE) d_col[pB] = sB;
    }
}

// ---------------- propagation: warp per node, 2 edges per LDG.128 -----------
// (R7/R9/R10 structure — empirical optimum; DO NOT MODIFY)
__device__ __forceinline__ void acc8(float* a, uint4 v) {
    float2 f;
    f = __half22float2(*(__half2*)&v.x); a[0] += f.x; a[1] += f.y;
    f = __half22float2(*(__half2*)&v.y); a[2] += f.x; a[3] += f.y;
    f = __half22float2(*(__half2*)&v.z); a[4] += f.x; a[5] += f.y;
    f = __half22float2(*(__half2*)&v.w); a[6] += f.x; a[7] += f.y;
}

__global__ void __launch_bounds__(256) propagate_kernel(int k) {
    const uint4* __restrict__ xin  = (const uint4*)d_hx[k - 1];
    uint4* __restrict__       xout = (uint4*)d_hx[k];

    int warp = (blockIdx.x * blockDim.x + threadIdx.x) >> 5;
    int lane = threadIdx.x & 31;
    if (warp >= NN) return;
    int sub = lane >> 4;       // 0 or 1
    int sl  = lane & 15;       // uint4 column within node row

    int beg = d_rowptr[warp];
    int end = d_rowptr[warp + 1];
    float a[8] = {0.f, 0.f, 0.f, 0.f, 0.f, 0.f, 0.f, 0.f};

    int e = beg;
    for (; e + 8 <= end; e += 8) {
        int s0 = d_col[e + 0], s1 = d_col[e + 1];
        int s2 = d_col[e + 2], s3 = d_col[e + 3];
        int s4 = d_col[e + 4], s5 = d_col[e + 5];
        int s6 = d_col[e + 6], s7 = d_col[e + 7];
        uint4 v0 = xin[(sub ? s1 : s0) * 16 + sl];
        uint4 v1 = xin[(sub ? s3 : s2) * 16 + sl];
        uint4 v2 = xin[(sub ? s5 : s4) * 16 + sl];
        uint4 v3 = xin[(sub ? s7 : s6) * 16 + sl];
        acc8(a, v0); acc8(a, v1); acc8(a, v2); acc8(a, v3);
    }
    for (; e + 2 <= end; e += 2) {
        int sa = d_col[e], sb = d_col[e + 1];
        uint4 v = xin[(sub ? sb : sa) * 16 + sl];
        acc8(a, v);
    }
    if (e < end && sub == 0) {
        uint4 v = xin[d_col[e] * 16 + sl];
        acc8(a, v);
    }

    #pragma unroll
    for (int j = 0; j < 8; j++)
        a[j] += __shfl_xor_sync(0xFFFFFFFFu, a[j], 16);

    if (sub == 0) {
        float nw = d_norm[warp];
        float w2 = nw * nw;
        __half2 h0 = __floats2half2_rn(w2 * a[0], w2 * a[1]);
        __half2 h1 = __floats2half2_rn(w2 * a[2], w2 * a[3]);
        __half2 h2 = __floats2half2_rn(w2 * a[4], w2 * a[5]);
        __half2 h3 = __floats2half2_rn(w2 * a[6], w2 * a[7]);
        uint4 o;
        o.x = *(unsigned*)&h0; o.y = *(unsigned*)&h1;
        o.z = *(unsigned*)&h2; o.w = *(unsigned*)&h3;
        xout[warp * 16 + sl] = o;
    }
}

// ---------------- tensor-core fused MLP ------------------------------------
// out = relu((0.1 * rnorm_i * sum_b x'_b) @ W1) @ W2
// 2 row-tiles (128 rows) per block: weights loaded once, reused.
#define YST  136
#define W1ST 136
#define W2ST 72
#define HST  136
#define OFF_W1 0
#define OFF_W2 17408
#define OFF_Y  26624
#define OFF_H  35328
#define GEMM_SMEM (44032 * 2)

__device__ __forceinline__ void ldsm_x4(unsigned addr, unsigned& r0, unsigned& r1,
                                        unsigned& r2, unsigned& r3) {
    asm volatile("ldmatrix.sync.aligned.m8n8.x4.shared.b16 {%0,%1,%2,%3}, [%4];"
                 : "=r"(r0), "=r"(r1), "=r"(r2), "=r"(r3) : "r"(addr));
}
__device__ __forceinline__ void ldsm_x2t(unsigned addr, unsigned& r0, unsigned& r1) {
    asm volatile("ldmatrix.sync.aligned.m8n8.x2.trans.shared.b16 {%0,%1}, [%2];"
                 : "=r"(r0), "=r"(r1) : "r"(addr));
}
__device__ __forceinline__ void mma_16816(float& d0, float& d1, float& d2, float& d3,
                                          unsigned a0, unsigned a1, unsigned a2, unsigned a3,
                                          unsigned b0, unsigned b1) {
    asm volatile("mma.sync.aligned.m16n8k16.row.col.f32.f16.f16.f32 "
                 "{%0,%1,%2,%3}, {%4,%5,%6,%7}, {%8,%9}, {%0,%1,%2,%3};"
                 : "+f"(d0), "+f"(d1), "+f"(d2), "+f"(d3)
                 : "r"(a0), "r"(a1), "r"(a2), "r"(a3), "r"(b0), "r"(b1));
}

__global__ void gemm_fused_kernel(float* __restrict__ out) {
    extern __shared__ __half sh[];
    unsigned sbase = (unsigned)__cvta_generic_to_shared(sh);

    int t = threadIdx.x;        // 128 threads, 4 warps
    int lane = t & 31;
    int w = t >> 5;

    // ---- load weights once per block ----
    {
        const uint4* g = (const uint4*)d_W1h;
        #pragma unroll
        for (int i = 0; i < 16; i++) {
            int idx = i * 128 + t;
            int r = idx >> 4, c4 = idx & 15;
            *(uint4*)&sh[OFF_W1 + r * W1ST + c4 * 8] = g[idx];
        }
    }
    {
        const uint4* g = (const uint4*)d_W2h;
        #pragma unroll
        for (int i = 0; i < 8; i++) {
            int idx = i * 128 + t;
            int r = idx >> 3, c4 = idx & 7;
            *(uint4*)&sh[OFF_W2 + r * W2ST + c4 * 8] = g[idx];
        }
    }

    int g_  = lane >> 3;
    int ar  = (g_ & 1) * 8 + (lane & 7);
    int ac  = (g_ >> 1) * 8;
    int bk  = lane & 15;

    // ---- two 64-row tiles per block ----
    for (int t2 = 0; t2 < 2; t2++) {
        int rowBase = blockIdx.x * 128 + t2 * 64;
        if (rowBase >= NN) break;

        // build Y tile = fp16(0.1 * rnorm * sum_b x'_b)
        // (no barrier needed before: prior iteration's sH reads finish
        //  before any thread passes the __syncthreads below)
        #pragma unroll
        for (int i = 0; i < 16; i++) {
            int idx = i * 128 + t;          // 64 rows x 32 uint2 cols
            int r = idx >> 5, c = idx & 31;
            int gr = rowBase + r;
            float s0 = 0.f, s1 = 0.f, s2 = 0.f, s3 = 0.f;
            float scl = 0.f;
            if (gr < NN) {
                scl = 0.1f * d_rnorm[gr];
                #pragma unroll
                for (int b = 0; b < 5; b++) {
                    uint2 v = d_hx[b][gr * 32 + c];
                    float2 f0 = __half22float2(*(__half2*)&v.x);
                    float2 f1 = __half22float2(*(__half2*)&v.y);
                    s0 += f0.x; s1 += f0.y; s2 += f1.x; s3 += f1.y;
                }
            }
            __half2 p0 = __floats2half2_rn(scl * s0, scl * s1);
            __half2 p1 = __floats2half2_rn(scl * s2, scl * s3);
            uint2 o;
            o.x = *(unsigned*)&p0;
            o.y = *(unsigned*)&p1;
            *(uint2*)&sh[OFF_Y + r * YST + c * 4] = o;
        }
        __syncthreads();

        // phase A: H = relu(Y @ W1)
        {
            unsigned aF[8][4];
            #pragma unroll
            for (int ks = 0; ks < 8; ks++) {
                unsigned addr = sbase + (OFF_Y + (w * 16 + ar) * YST + ks * 16 + ac) * 2;
                ldsm_x4(addr, aF[ks][0], aF[ks][1], aF[ks][2], aF[ks][3]);
            }
            #pragma unroll
            for (int nt = 0; nt < 16; nt++) {
                float d0 = 0.f, d1 = 0.f, d2 = 0.f, d3 = 0.f;
                #pragma unroll
                for (int ks = 0; ks < 8; ks++) {
                    unsigned b0, b1;
                    unsigned baddr = sbase + (OFF_W1 + (ks * 16 + bk) * W1ST + nt * 8) * 2;
                    ldsm_x2t(baddr, b0, b1);
                    mma_16816(d0, d1, d2, d3, aF[ks][0], aF[ks][1], aF[ks][2], aF[ks][3], b0, b1);
                }
                int hr = w * 16 + (lane >> 2);
                int hc = nt * 8 + (lane & 3) * 2;
                __half2 h01 = __floats2half2_rn(fmaxf(d0, 0.f), fmaxf(d1, 0.f));
                __half2 h23 = __floats2half2_rn(fmaxf(d2, 0.f), fmaxf(d3, 0.f));
                *(unsigned*)&sh[OFF_H + hr * HST + hc]       = *(unsigned*)&h01;
                *(unsigned*)&sh[OFF_H + (hr + 8) * HST + hc] = *(unsigned*)&h23;
            }
        }
        __syncthreads();

        // phase B: out = H @ W2
        {
            unsigned hF[8][4];
            #pragma unroll
            for (int ks = 0; ks < 8; ks++) {
                unsigned addr = sbase + (OFF_H + (w * 16 + ar) * HST + ks * 16 + ac) * 2;
                ldsm_x4(addr, hF[ks][0], hF[ks][1], hF[ks][2], hF[ks][3]);
            }
            #pragma unroll
            for (int nt = 0; nt < 8; nt++) {
                float d0 = 0.f, d1 = 0.f, d2 = 0.f, d3 = 0.f;
                #pragma unroll
                for (int ks = 0; ks < 8; ks++) {
                    unsigned b0, b1;
                    unsigned baddr = sbase + (OFF_W2 + (ks * 16 + bk) * W2ST + nt * 8) * 2;
                    ldsm_x2t(baddr, b0, b1);
                    mma_16816(d0, d1, d2, d3, hF[ks][0], hF[ks][1], hF[ks][2], hF[ks][3], b0, b1);
                }
                int row = w * 16 + (lane >> 2);
                int c   = nt * 8 + (lane & 3) * 2;
                int gr0 = rowBase + row;
                int gr1 = gr0 + 8;
                if (gr0 < NN) *(float2*)&out[gr0 * DOUT + c] = make_float2(d0, d1);
                if (gr1 < NN) *(float2*)&out[gr1 * DOUT + c] = make_float2(d2, d3);
            }
        }
        __syncthreads();   // protect sY/sH reuse for next tile
    }
}

// ---------------- launch ----------------
extern "C" void kernel_launch(void* const* d_in, const int* in_sizes, int n_in,
                              void* d_out, int out_size) {
    const float* feats = (const float*)d_in[0];
    const float* W1    = (const float*)d_in[1];
    const float* W2    = (const float*)d_in[2];
    const int*   ei32  = (const int*)d_in[3];
    float*       out   = (float*)d_out;

    cudaFuncSetAttribute(gemm_fused_kernel,
                         cudaFuncAttributeMaxDynamicSharedMemorySize, GEMM_SMEM);

    zero_prep_kernel<<<(NN + 255) / 256, 256>>>(ei32, W1, W2);
    hist_kernel<<<(NE / 4 + 255) / 256, 256>>>(ei32);
    scan1_kernel<<<SCAN_B, 1024>>>();
    post_scan_kernel<<<(NN * 16 + 255) / 256, 256>>>(feats);   // fixup + init
    fill_kernel<<<(NE / 2 + 255) / 256, 256>>>(ei32);

    int prop_grid = (NN * 32 + 255) / 256;
    propagate_kernel<<<prop_grid, 256>>>(1);
    propagate_kernel<<<prop_grid, 256>>>(2);
    propagate_kernel<<<prop_grid, 256>>>(3);
    propagate_kernel<<<prop_grid, 256>>>(4);

    gemm_fused_kernel<<<(NN + 127) / 128, 128, GEMM_SMEM>>>(out);
}

// round 17
// speedup vs baseline: 1.0517x; 1.0116x over previous
#include <cuda_runtime.h>
#include <cuda_fp16.h>
#include <math.h>

#define NN 100000
#define NE 1600000
#define D 128
#define DOUT 64

// ---------------- scratch (static device globals; no allocs) ----------------
__device__ uint2  d_hx[5][NN * 32];   // pre-scaled states x'_k = norm*x_k, fp16
__device__ int    d_col[NE];          // src index per CSR slot
__device__ __half d_W1h[D * D];
__device__ __half d_W2h[D * DOUT];
__device__ int    d_deg[NN];
__device__ float  d_norm[NN];         // deg^-0.5
__device__ float  d_rnorm[NN];        // deg^+0.5
__device__ int    d_rowptr[NN + 1];
__device__ int    d_cursor[NN];
__device__ int    d_bsums[128];
__device__ int    d_is64;

#define SCAN_B 98
#define FIXUP_B ((NN + 255) / 256)    // 391
#define N_TILES ((NN + 63) / 64)      // 1563
#define GEMM_GRID 296                 // 2 blocks/SM x 148 SMs

// ---------------- zero deg + weight convert + dtype detect ------------------
__global__ void zero_prep_kernel(const int* __restrict__ ei32,
                                 const float* __restrict__ W1,
                                 const float* __restrict__ W2) {
    int i = blockIdx.x * blockDim.x + threadIdx.x;
    if (i < NN) d_deg[i] = 0;
    if (i < D * D) d_W1h[i] = __float2half(W1[i]);
    if (i < D * DOUT) d_W2h[i] = __float2half(W2[i]);
    if (i == 0) {
        int all_zero = 1;
        #pragma unroll
        for (int j = 0; j < 32; j++)
            if (ei32[2 * j + 1] != 0) all_zero = 0;
        d_is64 = all_zero;
    }
}

__device__ __forceinline__ int clampn(int v) {
    return (v < 0) ? 0 : (v >= NN ? NN - 1 : v);
}

// ---------------- CSR build ----------------
// hist: 4 edges per thread
__global__ void hist_kernel(const int* __restrict__ ei32) {
    int q = blockIdx.x * blockDim.x + threadIdx.x;
    int e = q * 4;
    if (e < NE) {
        int d0, d1, d2, d3;
        if (d_is64) {
            int4 a = *(const int4*)&ei32[2 * (NE + e)];
            int4 b = *(const int4*)&ei32[2 * (NE + e) + 4];
            d0 = a.x; d1 = a.z; d2 = b.x; d3 = b.z;
        } else {
            int4 v = *(const int4*)&ei32[NE + e];
            d0 = v.x; d1 = v.y; d2 = v.z; d3 = v.w;
        }
        atomicAdd(&d_deg[clampn(d0)], 1);
        atomicAdd(&d_deg[clampn(d1)], 1);
        atomicAdd(&d_deg[clampn(d2)], 1);
        atomicAdd(&d_deg[clampn(d3)], 1);
    }
}

// per-block prefix + norm/rnorm; raw block totals to d_bsums
__global__ void scan1_kernel() {
    __shared__ int s[1024];
    int tid = threadIdx.x;
    int idx = blockIdx.x * 1024 + tid;
    int c = (idx < NN) ? d_deg[idx] : 0;
    if (idx < NN) {
        float dg = fmaxf((float)c, 1.0f);
        d_norm[idx]  = rsqrtf(dg);
        d_rnorm[idx] = sqrtf(dg);
    }
    s[tid] = c;
    __syncthreads();
    #pragma unroll
    for (int off = 1; off < 1024; off <<= 1) {
        int v = (tid >= off) ? s[tid - off] : 0;
        __syncthreads();
        s[tid] += v;
        __syncthreads();
    }
    if (idx < NN) d_rowptr[idx] = s[tid] - c;
    if (tid == 1023) d_bsums[blockIdx.x] = s[1023];   // raw totals
}

// merged: scan fix-up (blocks 0..390) + init x'_0 (all 6250 blocks, 32B/thread)
__global__ void post_scan_kernel(const float* __restrict__ feats) {
    __shared__ int red[256];
    int tid = threadIdx.x;
    int b   = blockIdx.x;

    if (b < FIXUP_B) {
        int bucket = b >> 2;                 // (i >> 10), constant per block
        int partial = 0;
        for (int j = tid; j < bucket; j += 256) partial += d_bsums[j];
        red[tid] = partial;
        __syncthreads();
        #pragma unroll
        for (int off = 128; off > 0; off >>= 1) {
            if (tid < off) red[tid] += red[tid + off];
            __syncthreads();
        }
        int base = red[0];
        int i = b * 256 + tid;
        if (i < NN) {
            int r = d_rowptr[i] + base;
            d_rowptr[i] = r;
            d_cursor[i] = r;
        }
        if (i == 0) d_rowptr[NN] = NE;
    }

    // init: x'_0 = fp16(norm * feats), 2 uint2 outputs (32B) per thread
    int j = (b * 256 + tid) * 2;           // uint2 index space NN*32
    if (j < NN * 32) {
        float nw = d_norm[j >> 5];         // j, j+1 same node (32 cols/node)
        float4 va = ((const float4*)feats)[j];
        float4 vb = ((const float4*)feats)[j + 1];
        __half2 p0 = __floats2half2_rn(nw * va.x, nw * va.y);
        __half2 p1 = __floats2half2_rn(nw * va.z, nw * va.w);
        __half2 p2 = __floats2half2_rn(nw * vb.x, nw * vb.y);
        __half2 p3 = __floats2half2_rn(nw * vb.z, nw * vb.w);
        uint4 o;
        o.x = *(unsigned*)&p0; o.y = *(unsigned*)&p1;
        o.z = *(unsigned*)&p2; o.w = *(unsigned*)&p3;
        *(uint4*)&d_hx[0][j] = o;
    }
}

// fill: 2 edges per thread, vectorized index loads
__global__ void fill_kernel(const int* __restrict__ ei32) {
    int p = blockIdx.x * blockDim.x + threadIdx.x;
    int e = p * 2;
    if (e < NE) {
        int sA, sB, dA, dB;
        if (d_is64) {
            int4 sv = *(const int4*)&ei32[2 * e];
            int4 dv = *(const int4*)&ei32[2 * (NE + e)];
            sA = sv.x; sB = sv.z; dA = dv.x; dB = dv.z;
        } else {
            int2 sv = *(const int2*)&ei32[e];
            int2 dv = *(const int2*)&ei32[NE + e];
            sA = sv.x; sB = sv.y; dA = dv.x; dB = dv.y;
        }
        sA = clampn(sA); sB = clampn(sB);
        dA = clampn(dA); dB = clampn(dB);
        int pA = atomicAdd(&d_cursor[dA], 1);
        if (pA < NE) d_col[pA] = sA;
        int pB = atomicAdd(&d_cursor[dB], 1);
        if (pB < NE) d_col[pB] = sB;
    }
}

// ---------------- propagation: warp per node, 2 edges per LDG.128 -----------
// (R7/R9/R10 structure — empirical optimum; DO NOT MODIFY)
__device__ __forceinline__ void acc8(float* a, uint4 v) {
    float2 f;
    f = __half22float2(*(__half2*)&v.x); a[0] += f.x; a[1] += f.y;
    f = __half22float2(*(__half2*)&v.y); a[2] += f.x; a[3] += f.y;
    f = __half22float2(*(__half2*)&v.z); a[4] += f.x; a[5] += f.y;
    f = __half22float2(*(__half2*)&v.w); a[6] += f.x; a[7] += f.y;
}

__global__ void __launch_bounds__(256) propagate_kernel(int k) {
    const uint4* __restrict__ xin  = (const uint4*)d_hx[k - 1];
    uint4* __restrict__       xout = (uint4*)d_hx[k];

    int warp = (blockIdx.x * blockDim.x + threadIdx.x) >> 5;
    int lane = threadIdx.x & 31;
    if (warp >= NN) return;
    int sub = lane >> 4;       // 0 or 1
    int sl  = lane & 15;       // uint4 column within node row

    int beg = d_rowptr[warp];
    int end = d_rowptr[warp + 1];
    float a[8] = {0.f, 0.f, 0.f, 0.f, 0.f, 0.f, 0.f, 0.f};

    int e = beg;
    for (; e + 8 <= end; e += 8) {
        int s0 = d_col[e + 0], s1 = d_col[e + 1];
        int s2 = d_col[e + 2], s3 = d_col[e + 3];
        int s4 = d_col[e + 4], s5 = d_col[e + 5];
        int s6 = d_col[e + 6], s7 = d_col[e + 7];
        uint4 v0 = xin[(sub ? s1 : s0) * 16 + sl];
        uint4 v1 = xin[(sub ? s3 : s2) * 16 + sl];
        uint4 v2 = xin[(sub ? s5 : s4) * 16 + sl];
        uint4 v3 = xin[(sub ? s7 : s6) * 16 + sl];
        acc8(a, v0); acc8(a, v1); acc8(a, v2); acc8(a, v3);
    }
    for (; e + 2 <= end; e += 2) {
        int sa = d_col[e], sb = d_col[e + 1];
        uint4 v = xin[(sub ? sb : sa) * 16 + sl];
        acc8(a, v);
    }
    if (e < end && sub == 0) {
        uint4 v = xin[d_col[e] * 16 + sl];
        acc8(a, v);
    }

    #pragma unroll
    for (int j = 0; j < 8; j++)
        a[j] += __shfl_xor_sync(0xFFFFFFFFu, a[j], 16);

    if (sub == 0) {
        float nw = d_norm[warp];
        float w2 = nw * nw;
        __half2 h0 = __floats2half2_rn(w2 * a[0], w2 * a[1]);
        __half2 h1 = __floats2half2_rn(w2 * a[2], w2 * a[3]);
        __half2 h2 = __floats2half2_rn(w2 * a[4], w2 * a[5]);
        __half2 h3 = __floats2half2_rn(w2 * a[6], w2 * a[7]);
        uint4 o;
        o.x = *(unsigned*)&h0; o.y = *(unsigned*)&h1;
        o.z = *(unsigned*)&h2; o.w = *(unsigned*)&h3;
        xout[warp * 16 + sl] = o;
    }
}

// ---------------- tensor-core fused MLP ------------------------------------
// out = relu((0.1 * rnorm_i * sum_b x'_b) @ W1) @ W2
// persistent-style: grid-stride loop over 64-row tiles; weights loaded once.
#define YST  136
#define W1ST 136
#define W2ST 72
#define HST  136
#define OFF_W1 0
#define OFF_W2 17408
#define OFF_Y  26624
#define OFF_H  35328
#define GEMM_SMEM (44032 * 2)

__device__ __forceinline__ void ldsm_x4(unsigned addr, unsigned& r0, unsigned& r1,
                                        unsigned& r2, unsigned& r3) {
    asm volatile("ldmatrix.sync.aligned.m8n8.x4.shared.b16 {%0,%1,%2,%3}, [%4];"
                 : "=r"(r0), "=r"(r1), "=r"(r2), "=r"(r3) : "r"(addr));
}
__device__ __forceinline__ void ldsm_x2t(unsigned addr, unsigned& r0, unsigned& r1) {
    asm volatile("ldmatrix.sync.aligned.m8n8.x2.trans.shared.b16 {%0,%1}, [%2];"
                 : "=r"(r0), "=r"(r1) : "r"(addr));
}
__device__ __forceinline__ void mma_16816(float& d0, float& d1, float& d2, float& d3,
                                          unsigned a0, unsigned a1, unsigned a2, unsigned a3,
                                          unsigned b0, unsigned b1) {
    asm volatile("mma.sync.aligned.m16n8k16.row.col.f32.f16.f16.f32 "
                 "{%0,%1,%2,%3}, {%4,%5,%6,%7}, {%8,%9}, {%0,%1,%2,%3};"
                 : "+f"(d0), "+f"(d1), "+f"(d2), "+f"(d3)
                 : "r"(a0), "r"(a1), "r"(a2), "r"(a3), "r"(b0), "r"(b1));
}

__global__ void __launch_bounds__(128) gemm_fused_kernel(float* __restrict__ out) {
    extern __shared__ __half sh[];
    unsigned sbase = (unsigned)__cvta_generic_to_shared(sh);

    int t = threadIdx.x;        // 128 threads, 4 warps
    int lane = t & 31;
    int w = t >> 5;

    // ---- load weights once per block ----
    {
        const uint4* g = (const uint4*)d_W1h;
        #pragma unroll
        for (int i = 0; i < 16; i++) {
            int idx = i * 128 + t;
            int r = idx >> 4, c4 = idx & 15;
            *(uint4*)&sh[OFF_W1 + r * W1ST + c4 * 8] = g[idx];
        }
    }
    {
        const uint4* g = (const uint4*)d_W2h;
        #pragma unroll
        for (int i = 0; i < 8; i++) {
            int idx = i * 128 + t;
            int r = idx >> 3, c4 = idx & 7;
            *(uint4*)&sh[OFF_W2 + r * W2ST + c4 * 8] = g[idx];
        }
    }

    int g_  = lane >> 3;
    int ar  = (g_ & 1) * 8 + (lane & 7);
    int ac  = (g_ >> 1) * 8;
    int bk  = lane & 15;

    // ---- grid-stride loop over 64-row tiles ----
    for (int tile = blockIdx.x; tile < N_TILES; tile += gridDim.x) {
        int rowBase = tile * 64;

        // build Y tile = fp16(0.1 * rnorm * sum_b x'_b)
        #pragma unroll
        for (int i = 0; i < 16; i++) {
            int idx = i * 128 + t;          // 64 rows x 32 uint2 cols
            int r = idx >> 5, c = idx & 31;
            int gr = rowBase + r;
            float s0 = 0.f, s1 = 0.f, s2 = 0.f, s3 = 0.f;
            float scl = 0.f;
            if (gr < NN) {
                scl = 0.1f * d_rnorm[gr];
                #pragma unroll
                for (int b = 0; b < 5; b++) {
                    uint2 v = d_hx[b][gr * 32 + c];
                    float2 f0 = __half22float2(*(__half2*)&v.x);
                    float2 f1 = __half22float2(*(__half2*)&v.y);
                    s0 += f0.x; s1 += f0.y; s2 += f1.x; s3 += f1.y;
                }
            }
            __half2 p0 = __floats2half2_rn(scl * s0, scl * s1);
            __half2 p1 = __floats2half2_rn(scl * s2, scl * s3);
            uint2 o;
            o.x = *(unsigned*)&p0;
            o.y = *(unsigned*)&p1;
            *(uint2*)&sh[OFF_Y + r * YST + c * 4] = o;
        }
        __syncthreads();

        // phase A: H = relu(Y @ W1)
        {
            unsigned aF[8][4];
            #pragma unroll
            for (int ks = 0; ks < 8; ks++) {
                unsigned addr = sbase + (OFF_Y + (w * 16 + ar) * YST + ks * 16 + ac) * 2;
                ldsm_x4(addr, aF[ks][0], aF[ks][1], aF[ks][2], aF[ks][3]);
            }
            #pragma unroll
            for (int nt = 0; nt < 16; nt++) {
                float d0 = 0.f, d1 = 0.f, d2 = 0.f, d3 = 0.f;
                #pragma unroll
                for (int ks = 0; ks < 8; ks++) {
                    unsigned b0, b1;
                    unsigned baddr = sbase + (OFF_W1 + (ks * 16 + bk) * W1ST + nt * 8) * 2;
                    ldsm_x2t(baddr, b0, b1);
                    mma_16816(d0, d1, d2, d3, aF[ks][0], aF[ks][1], aF[ks][2], aF[ks][3], b0, b1);
                }
                int hr = w * 16 + (lane >> 2);
                int hc = nt * 8 + (lane & 3) * 2;
                __half2 h01 = __floats2half2_rn(fmaxf(d0, 0.f), fmaxf(d1, 0.f));
                __half2 h23 = __floats2half2_rn(fmaxf(d2, 0.f), fmaxf(d3, 0.f));
                *(unsigned*)&sh[OFF_H + hr * HST + hc]       = *(unsigned*)&h01;
                *(unsigned*)&sh[OFF_H + (hr + 8) * HST + hc] = *(unsigned*)&h23;
            }
        }
        __syncthreads();

        // phase B: out = H @ W2
        {
            unsigned hF[8][4];
            #pragma unroll
            for (int ks = 0; ks < 8; ks++) {
                unsigned addr = sbase + (OFF_H + (w * 16 + ar) * HST + ks * 16 + ac) * 2;
                ldsm_x4(addr, hF[ks][0], hF[ks][1], hF[ks][2], hF[ks][3]);
            }
            #pragma unroll
            for (int nt = 0; nt < 8; nt++) {
                float d0 = 0.f, d1 = 0.f, d2 = 0.f, d3 = 0.f;
                #pragma unroll
                for (int ks = 0; ks < 8; ks++) {
                    unsigned b0, b1;
                    unsigned baddr = sbase + (OFF_W2 + (ks * 16 + bk) * W2ST + nt * 8) * 2;
                    ldsm_x2t(baddr, b0, b1);
                    mma_16816(d0, d1, d2, d3, hF[ks][0], hF[ks][1], hF[ks][2], hF[ks][3], b0, b1);
                }
                int row = w * 16 + (lane >> 2);
                int c   = nt * 8 + (lane & 3) * 2;
                int gr0 = rowBase + row;
                int gr1 = gr0 + 8;
                if (gr0 < NN) *(float2*)&out[gr0 * DOUT + c] = make_float2(d0, d1);
                if (gr1 < NN) *(float2*)&out[gr1 * DOUT + c] = make_float2(d2, d3);
            }
        }
        __syncthreads();   // protect sY/sH reuse for next tile
    }
}

// ---------------- launch ----------------
extern "C" void kernel_launch(void* const* d_in, const int* in_sizes, int n_in,
                              void* d_out, int out_size) {
    const float* feats = (const float*)d_in[0];
    const float* W1    = (const float*)d_in[1];
    const float* W2    = (const float*)d_in[2];
    const int*   ei32  = (const int*)d_in[3];
    float*       out   = (float*)d_out;

    cudaFuncSetAttribute(gemm_fused_kernel,
                         cudaFuncAttributeMaxDynamicSharedMemorySize, GEMM_SMEM);

    zero_prep_kernel<<<(NN + 255) / 256, 256>>>(ei32, W1, W2);
    hist_kernel<<<(NE / 4 + 255) / 256, 256>>>(ei32);
    scan1_kernel<<<SCAN_B, 1024>>>();
    post_scan_kernel<<<(NN * 16 + 255) / 256, 256>>>(feats);   // fixup + init
    fill_kernel<<<(NE / 2 + 255) / 256, 256>>>(ei32);

    int prop_grid = (NN * 32 + 255) / 256;
    propagate_kernel<<<prop_grid, 256>>>(1);
    propagate_kernel<<<prop_grid, 256>>>(2);
    propagate_kernel<<<prop_grid, 256>>>(3);
    propagate_kernel<<<prop_grid, 256>>>(4);

    gemm_fused_kernel<<<GEMM_GRID, 128, GEMM_SMEM>>>(out);
}